// round 13
// baseline (speedup 1.0000x reference)
#include <cuda_runtime.h>
#include <cuda_fp16.h>
#include <math.h>

// Problem constants
#define LS       32
#define SB       1024            // S = LS*LS
#define NB       16              // batch
#define NE       1024            // embedding
#define BE       (NB*NE)         // 16384: stride between spatial positions
#define S_TOT    (SB*NB*NE)      // 16,777,216 elements

// fp16 scratch, pair-interleaved layout (128 MB total):
//   half index = dir*S_TOT + ((i*16 + jpair)*BE + b*NE + e)*2 + parity
// parity 0 = physical column 2*jpair, parity 1 = 2*jpair+1.
__device__ __half g_scrh[4ULL * S_TOT];

typedef unsigned long long u64;

__device__ __forceinline__ float sigm(float v) { return 1.0f / (1.0f + expf(-v)); }

// ---- packed f32x2 helpers (sm_103a paired-fp32 ops, PTX-only) ----
__device__ __forceinline__ u64 pack2(float lo, float hi) {
    u64 r; asm("mov.b64 %0, {%1,%2};" : "=l"(r) : "f"(lo), "f"(hi)); return r;
}
__device__ __forceinline__ float2 unpack2(u64 v) {
    float2 r; asm("mov.b64 {%0,%1}, %2;" : "=f"(r.x), "=f"(r.y) : "l"(v)); return r;
}
__device__ __forceinline__ u64 fma2(u64 a, u64 b, u64 c) {
    u64 d; asm("fma.rn.f32x2 %0,%1,%2,%3;" : "=l"(d) : "l"(a), "l"(b), "l"(c)); return d;
}
__device__ __forceinline__ u64 mul2(u64 a, u64 b) {
    u64 d; asm("mul.rn.f32x2 %0,%1,%2;" : "=l"(d) : "l"(a), "l"(b)); return d;
}

__device__ __forceinline__ void st_h2_cs(__half* p, __half2 v) {
    unsigned raw = *reinterpret_cast<unsigned*>(&v);
    asm volatile("st.global.cs.u32 [%0], %1;" :: "l"(p), "r"(raw) : "memory");
}

// ---------------------------------------------------------------------------
// Scan kernel — EXACT round-7 source (best measured: ~111.5us).
// One thread per (dir, b, e). 2D SSM recurrence (= causal 2D conv with the
// impulse response) on the direction-flipped image, plus the two 1D
// boundary-correction recurrences implementing the reference's K row-0/col-0
// doubling. N=2 state pairs packed in f32x2 (11 ops/pixel).
//
// 128-thread CTAs (4 warps -> all 4 SMSPs). 4-row register blocking.
// Columns in pairs: one coalesced STG.32 (half2) per row per pair into
// pair-interleaved fp16 scratch; next pair's 8 input loads prefetched.
// Per-column carries in SMEM: z f32x2 (8B) + t half2 (4B) -> 48KB static
// -> 4 CTAs/SM, 512 CTAs, 16 warps/SM.
// ---------------------------------------------------------------------------
__global__ void __launch_bounds__(128, 4) ssm_scan(
    const float* __restrict__ x,
    const float* __restrict__ A1v, const float* __restrict__ A2v,
    const float* __restrict__ A3v, const float* __restrict__ A4v,
    const float* __restrict__ B1v, const float* __restrict__ B2v,
    const float* __restrict__ C1v, const float* __restrict__ C2v)
{
    __shared__ u64     sh_z[LS][128];   // 32 KB: vertical carry, f32x2
    __shared__ __half2 sh_t[LS][128];   // 16 KB: col-0 correction, half2

    const int tid = threadIdx.x;
    const int g   = blockIdx.x * 128 + tid;
    const int e   = g & (NE - 1);
    const int b   = (g >> 10) & (NB - 1);
    const int dir = g >> 14;                 // 0..3
    const int h   = (dir << 6) | (e & 63);   // kernel channel
    const bool fi = (dir & 1) != 0;          // flip rows (axis -2)
    const bool fj = (dir & 2) != 0;          // flip cols (axis -1)

    const float scale = 0.70710678118654752440f;  // sqrt(1/N), N=2

    float p1[2], p2[2], p3[2], p4[2], q1[2], q2[2], r1[2], r2[2];
#pragma unroll
    for (int n = 0; n < 2; n++) {
        p1[n] = sigm(A1v[2 * h + n]);
        p2[n] = sigm(A2v[2 * h + n]);
        p3[n] = sigm(A3v[2 * h + n]);
        p4[n] = sigm(A4v[2 * h + n]);
        q1[n] = sigm(B1v[2 * h + n]);
        q2[n] = sigm(B2v[2 * h + n]);
        r1[n] = scale * C1v[2 * h + n];
        r2[n] = scale * C2v[2 * h + n];
    }
    const u64 a1  = pack2(p1[0], p1[1]);
    const u64 a32 = pack2(p3[0] * p2[0], p3[1] * p2[1]);
    const u64 a31 = pack2(p3[0] * q1[0], p3[1] * q1[1]);
    const u64 bb2 = pack2(q2[0], q2[1]);
    const u64 a4  = pack2(p4[0], p4[1]);
    const u64 c1p = pack2(r1[0] / p3[0], r1[1] / p3[1]);
    const u64 c2  = pack2(r2[0], r2[1]);
    const u64 cw1 = pack2(r1[0] * (p1[0] * q1[0] + p2[0] * q2[0]),
                          r1[1] * (p1[1] * q1[1] + p2[1] * q2[1]));
    const u64 cw2 = pack2(r2[0] * (p3[0] * q1[0] + p4[0] * q2[0]),
                          r2[1] * (p3[1] * q1[1] + p4[1] * q2[1]));

    // zero the private per-column carries (no cross-thread sharing -> no syncs)
#pragma unroll
    for (int j = 0; j < LS; j++) {
        sh_z[j][tid] = 0ULL;
        sh_t[j][tid] = __floats2half2_rn(0.f, 0.f);
    }

    const float* xp = x + b * NE + e;
    __half* op = g_scrh + (size_t)dir * S_TOT + (size_t)(b * NE + e) * 2;

    for (int ib = 0; ib < 8; ib++) {   // 8 blocks of 4 rows
        u64 p[4], xv[4], ss[4];
        float upf[4];
#pragma unroll
        for (int r = 0; r < 4; r++) { p[r] = xv[r] = ss[r] = 0ULL; upf[r] = 0.f; }

        int rowoff[4];   // float offset into x == half offset into scratch row
#pragma unroll
        for (int r = 0; r < 4; r++) {
            int i  = ib * 4 + r;
            int ip = fi ? (LS - 1 - i) : i;
            rowoff[r] = (ip * LS) * BE;
        }

        // preload pair 0 (logical columns 0,1)
        float u0[4], u1[4], n0[4], n1[4];
        {
            const int c0 = (fj ? (LS - 1) : 0) * BE;
            const int c1 = (fj ? (LS - 2) : 1) * BE;
#pragma unroll
            for (int r = 0; r < 4; r++) {
                u0[r] = xp[rowoff[r] + c0];
                u1[r] = xp[rowoff[r] + c1];
            }
        }

        for (int m = 0; m < 16; m++) {
            // prefetch next pair's 8 input loads
            if (m < 15) {
                const int c0n = (fj ? (LS - 3 - 2 * m) : (2 * m + 2)) * BE;
                const int c1n = (fj ? (LS - 4 - 2 * m) : (2 * m + 3)) * BE;
#pragma unroll
                for (int r = 0; r < 4; r++) {
                    n0[r] = xp[rowoff[r] + c0n];
                    n1[r] = xp[rowoff[r] + c1n];
                }
            }

            const int jl = 2 * m;
            u64 z0 = sh_z[jl][tid];
            u64 z1 = sh_z[jl + 1][tid];
            u64 t0, t1;
            {
                float2 tf0 = __half22float2(sh_t[jl][tid]);
                float2 tf1 = __half22float2(sh_t[jl + 1][tid]);
                t0 = pack2(tf0.x, tf0.y);
                t1 = pack2(tf1.x, tf1.y);
            }

            const int jph = fj ? (15 - m) : m;       // physical pair index
            const int sOff = jph * 2 * BE;           // half offset of pair

#pragma unroll
            for (int r = 0; r < 4; r++) {
                // ---- logical column jl ----
                const float usa = u0[r];
                const u64 u2a = pack2(usa, usa);
                const u64 upa = pack2(upf[r], upf[r]);
                u64 ns = fma2(a1, ss[r], upa);
                u64 nv = fma2(bb2, u2a, z0);
                u64 pn = fma2(a1, p[r], fma2(a32, xv[r], mul2(a31, u2a)));
                z0 = fma2(a4, nv, pn);
                u64 acc = fma2(c1p, pn,
                           fma2(cw1, ns,
                            fma2(cw2, t0, mul2(c2, nv))));
                t0 = fma2(a4, t0, u2a);
                float2 ava = unpack2(acc);
                const float ye = ava.x + ava.y;

                // ---- logical column jl+1 (u_prev = u0) ----
                const float usb = u1[r];
                const u64 u2b = pack2(usb, usb);
                u64 ns2 = fma2(a1, ns, u2a);
                u64 nv2 = fma2(bb2, u2b, z1);
                u64 pn2 = fma2(a1, pn, fma2(a32, nv, mul2(a31, u2b)));
                z1 = fma2(a4, nv2, pn2);
                u64 acc2 = fma2(c1p, pn2,
                            fma2(cw1, ns2,
                             fma2(cw2, t1, mul2(c2, nv2))));
                t1 = fma2(a4, t1, u2b);
                float2 avb = unpack2(acc2);
                const float yo = avb.x + avb.y;

                // roll states past the pair
                p[r]  = pn2;
                xv[r] = nv2;
                ss[r] = ns2;
                upf[r] = usb;

                // one coalesced half2 store per row per pair
                __half2 hv = fj ? __floats2half2_rn(yo, ye)
                                : __floats2half2_rn(ye, yo);
                st_h2_cs(op + rowoff[r] + sOff, hv);
            }
            sh_z[jl][tid] = z0;
            sh_z[jl + 1][tid] = z1;
            {
                float2 g0 = unpack2(t0);
                float2 g1 = unpack2(t1);
                sh_t[jl][tid]     = __floats2half2_rn(g0.x, g0.y);
                sh_t[jl + 1][tid] = __floats2half2_rn(g1.x, g1.y);
            }

#pragma unroll
            for (int r = 0; r < 4; r++) { u0[r] = n0[r]; u1[r] = n1[r]; }
        }
    }
}

// ---------------------------------------------------------------------------
// Epilogue: out = silu( y0+y1+y2+y3 + x*omega ). Each thread: 4 e's x 2
// physical columns (one scratch pair). Round-7 structure; only the silu
// math is fast-path (__expf + __fdividef).
// ---------------------------------------------------------------------------
__global__ void __launch_bounds__(256) ssm_epilogue(
    const float* __restrict__ x,
    const float* __restrict__ omega,
    float* __restrict__ out)
{
    const int t  = blockIdx.x * 256 + threadIdx.x;   // 0 .. S_TOT/8
    const int e0 = (t & 255) * 4;                    // 4-aligned e
    const int bi = (t >> 8) & 15;
    const int sp = t >> 12;                          // i*16 + jpair, [0,512)

    const unsigned hb = (unsigned)sp * (BE * 2) + (unsigned)(bi * NE + e0) * 2;

    float accE[4] = {0.f, 0.f, 0.f, 0.f};
    float accO[4] = {0.f, 0.f, 0.f, 0.f};
#pragma unroll
    for (int d = 0; d < 4; d++) {
        uint4 raw = __ldcs(reinterpret_cast<const uint4*>(
            g_scrh + (size_t)d * S_TOT + hb));
        const unsigned* rw = reinterpret_cast<const unsigned*>(&raw);
#pragma unroll
        for (int k = 0; k < 4; k++) {
            __half2 hv = *reinterpret_cast<const __half2*>(&rw[k]);
            float2 fv = __half22float2(hv);
            accE[k] += fv.x;   // physical col 2*jpair
            accO[k] += fv.y;   // physical col 2*jpair+1
        }
    }

    const int s0 = sp * 2 * BE + bi * NE + e0;   // (i*32 + 2*jpair)*BE + ...
    const int s1 = s0 + BE;

    float4 x0 = *reinterpret_cast<const float4*>(x + s0);
    float4 x1 = *reinterpret_cast<const float4*>(x + s1);
    float4 om = *reinterpret_cast<const float4*>(omega + e0);

    float zE[4], zO[4];
    zE[0] = accE[0] + x0.x * om.x;  zO[0] = accO[0] + x1.x * om.x;
    zE[1] = accE[1] + x0.y * om.y;  zO[1] = accO[1] + x1.y * om.y;
    zE[2] = accE[2] + x0.z * om.z;  zO[2] = accO[2] + x1.z * om.z;
    zE[3] = accE[3] + x0.w * om.w;  zO[3] = accO[3] + x1.w * om.w;

    float4 r0, r1;
    r0.x = __fdividef(zE[0], 1.0f + __expf(-zE[0]));
    r0.y = __fdividef(zE[1], 1.0f + __expf(-zE[1]));
    r0.z = __fdividef(zE[2], 1.0f + __expf(-zE[2]));
    r0.w = __fdividef(zE[3], 1.0f + __expf(-zE[3]));
    r1.x = __fdividef(zO[0], 1.0f + __expf(-zO[0]));
    r1.y = __fdividef(zO[1], 1.0f + __expf(-zO[1]));
    r1.z = __fdividef(zO[2], 1.0f + __expf(-zO[2]));
    r1.w = __fdividef(zO[3], 1.0f + __expf(-zO[3]));
    *reinterpret_cast<float4*>(out + s0) = r0;
    *reinterpret_cast<float4*>(out + s1) = r1;
}

extern "C" void kernel_launch(void* const* d_in, const int* in_sizes, int n_in,
                              void* d_out, int out_size)
{
    const float* x   = (const float*)d_in[0];
    const float* A1v = (const float*)d_in[1];
    const float* A2v = (const float*)d_in[2];
    const float* A3v = (const float*)d_in[3];
    const float* A4v = (const float*)d_in[4];
    const float* B1v = (const float*)d_in[5];
    const float* B2v = (const float*)d_in[6];
    const float* C1v = (const float*)d_in[7];
    const float* C2v = (const float*)d_in[8];
    const float* om  = (const float*)d_in[9];
    float* out = (float*)d_out;

    // 4 dirs * 16 b * 1024 e = 65536 threads; 512 CTAs of 128 -> 1 wave,
    // 4 warps/CTA covering all 4 SMSPs.
    ssm_scan<<<512, 128>>>(x, A1v, A2v, A3v, A4v, B1v, B2v, C1v, C2v);
    ssm_epilogue<<<S_TOT / 8 / 256, 256>>>(x, om, out);
}

// round 14
// speedup vs baseline: 1.4337x; 1.4337x over previous
#include <cuda_runtime.h>
#include <cuda_fp16.h>
#include <math.h>

// Problem constants
#define LS       32
#define SB       1024            // S = LS*LS
#define NB       16              // batch
#define NE       1024            // embedding
#define BE       (NB*NE)         // 16384: stride between spatial positions
#define S_TOT    (SB*NB*NE)      // 16,777,216 elements

// fp16 scratch, pair-interleaved layout (128 MB total):
//   half index = dir*S_TOT + ((i*16 + jpair)*BE + b*NE + e)*2 + parity
// parity 0 = physical column 2*jpair, parity 1 = 2*jpair+1.
__device__ __half g_scrh[4ULL * S_TOT];

typedef unsigned long long u64;

__device__ __forceinline__ float sigm(float v) { return 1.0f / (1.0f + expf(-v)); }

// ---- packed f32x2 helpers (sm_103a paired-fp32 ops, PTX-only) ----
__device__ __forceinline__ u64 pack2(float lo, float hi) {
    u64 r; asm("mov.b64 %0, {%1,%2};" : "=l"(r) : "f"(lo), "f"(hi)); return r;
}
__device__ __forceinline__ float2 unpack2(u64 v) {
    float2 r; asm("mov.b64 {%0,%1}, %2;" : "=f"(r.x), "=f"(r.y) : "l"(v)); return r;
}
__device__ __forceinline__ u64 fma2(u64 a, u64 b, u64 c) {
    u64 d; asm("fma.rn.f32x2 %0,%1,%2,%3;" : "=l"(d) : "l"(a), "l"(b), "l"(c)); return d;
}
__device__ __forceinline__ u64 mul2(u64 a, u64 b) {
    u64 d; asm("mul.rn.f32x2 %0,%1,%2;" : "=l"(d) : "l"(a), "l"(b)); return d;
}

__device__ __forceinline__ void st_h2_cs(__half* p, __half2 v) {
    unsigned raw = *reinterpret_cast<unsigned*>(&v);
    asm volatile("st.global.cs.u32 [%0], %1;" :: "l"(p), "r"(raw) : "memory");
}

// ---------------------------------------------------------------------------
// Scan kernel: one thread per (dir, b, e). 2D SSM recurrence (= causal 2D
// conv with the impulse response) on the direction-flipped image, plus the
// two 1D boundary-correction recurrences implementing the reference's
// K row-0/col-0 doubling. N=2 state pairs packed in f32x2 (11 ops/pixel).
//
// 128-thread CTAs (4 warps -> all 4 SMSPs). 4-row register blocking.
// Columns in pairs: one coalesced STG.32 (half2) per row per pair into
// pair-interleaved fp16 scratch; next pair's 8 input loads prefetched.
// Per-column carries in SMEM: z f32x2 (8B) + t half2 (4B) -> 48KB static
// -> 4 CTAs/SM, 512 CTAs, 16 warps/SM.
// ---------------------------------------------------------------------------
__global__ void __launch_bounds__(128, 4) ssm_scan(
    const float* __restrict__ x,
    const float* __restrict__ A1v, const float* __restrict__ A2v,
    const float* __restrict__ A3v, const float* __restrict__ A4v,
    const float* __restrict__ B1v, const float* __restrict__ B2v,
    const float* __restrict__ C1v, const float* __restrict__ C2v)
{
    __shared__ u64     sh_z[LS][128];   // 32 KB: vertical carry, f32x2
    __shared__ __half2 sh_t[LS][128];   // 16 KB: col-0 correction, half2

    const int tid = threadIdx.x;
    const int g   = blockIdx.x * 128 + tid;
    const int e   = g & (NE - 1);
    const int b   = (g >> 10) & (NB - 1);
    const int dir = g >> 14;                 // 0..3
    const int h   = (dir << 6) | (e & 63);   // kernel channel
    const bool fi = (dir & 1) != 0;          // flip rows (axis -2)
    const bool fj = (dir & 2) != 0;          // flip cols (axis -1)

    const float scale = 0.70710678118654752440f;  // sqrt(1/N), N=2

    float p1[2], p2[2], p3[2], p4[2], q1[2], q2[2], r1[2], r2[2];
#pragma unroll
    for (int n = 0; n < 2; n++) {
        p1[n] = sigm(A1v[2 * h + n]);
        p2[n] = sigm(A2v[2 * h + n]);
        p3[n] = sigm(A3v[2 * h + n]);
        p4[n] = sigm(A4v[2 * h + n]);
        q1[n] = sigm(B1v[2 * h + n]);
        q2[n] = sigm(B2v[2 * h + n]);
        r1[n] = scale * C1v[2 * h + n];
        r2[n] = scale * C2v[2 * h + n];
    }
    const u64 a1  = pack2(p1[0], p1[1]);
    const u64 a32 = pack2(p3[0] * p2[0], p3[1] * p2[1]);
    const u64 a31 = pack2(p3[0] * q1[0], p3[1] * q1[1]);
    const u64 bb2 = pack2(q2[0], q2[1]);
    const u64 a4  = pack2(p4[0], p4[1]);
    const u64 c1p = pack2(r1[0] / p3[0], r1[1] / p3[1]);
    const u64 c2  = pack2(r2[0], r2[1]);
    const u64 cw1 = pack2(r1[0] * (p1[0] * q1[0] + p2[0] * q2[0]),
                          r1[1] * (p1[1] * q1[1] + p2[1] * q2[1]));
    const u64 cw2 = pack2(r2[0] * (p3[0] * q1[0] + p4[0] * q2[0]),
                          r2[1] * (p3[1] * q1[1] + p4[1] * q2[1]));

    // zero the private per-column carries (no cross-thread sharing -> no syncs)
#pragma unroll
    for (int j = 0; j < LS; j++) {
        sh_z[j][tid] = 0ULL;
        sh_t[j][tid] = __floats2half2_rn(0.f, 0.f);
    }

    const float* xp = x + b * NE + e;
    __half* op = g_scrh + (size_t)dir * S_TOT + (size_t)(b * NE + e) * 2;

    for (int ib = 0; ib < 8; ib++) {   // 8 blocks of 4 rows
        u64 p[4], xv[4], ss[4];
        float upf[4];
#pragma unroll
        for (int r = 0; r < 4; r++) { p[r] = xv[r] = ss[r] = 0ULL; upf[r] = 0.f; }

        int rowoff[4];   // float offset into x == half offset into scratch row
#pragma unroll
        for (int r = 0; r < 4; r++) {
            int i  = ib * 4 + r;
            int ip = fi ? (LS - 1 - i) : i;
            rowoff[r] = (ip * LS) * BE;
        }

        // preload pair 0 (logical columns 0,1)
        float u0[4], u1[4], n0[4], n1[4];
        {
            const int c0 = (fj ? (LS - 1) : 0) * BE;
            const int c1 = (fj ? (LS - 2) : 1) * BE;
#pragma unroll
            for (int r = 0; r < 4; r++) {
                u0[r] = xp[rowoff[r] + c0];
                u1[r] = xp[rowoff[r] + c1];
            }
        }

        for (int m = 0; m < 16; m++) {
            // prefetch next pair's 8 input loads
            if (m < 15) {
                const int c0n = (fj ? (LS - 3 - 2 * m) : (2 * m + 2)) * BE;
                const int c1n = (fj ? (LS - 4 - 2 * m) : (2 * m + 3)) * BE;
#pragma unroll
                for (int r = 0; r < 4; r++) {
                    n0[r] = xp[rowoff[r] + c0n];
                    n1[r] = xp[rowoff[r] + c1n];
                }
            }

            const int jl = 2 * m;
            u64 z0 = sh_z[jl][tid];
            u64 z1 = sh_z[jl + 1][tid];
            u64 t0, t1;
            {
                float2 tf0 = __half22float2(sh_t[jl][tid]);
                float2 tf1 = __half22float2(sh_t[jl + 1][tid]);
                t0 = pack2(tf0.x, tf0.y);
                t1 = pack2(tf1.x, tf1.y);
            }

            const int jph = fj ? (15 - m) : m;       // physical pair index
            const int sOff = jph * 2 * BE;           // half offset of pair

#pragma unroll
            for (int r = 0; r < 4; r++) {
                // ---- logical column jl ----
                const float usa = u0[r];
                const u64 u2a = pack2(usa, usa);
                const u64 upa = pack2(upf[r], upf[r]);
                u64 ns = fma2(a1, ss[r], upa);
                u64 nv = fma2(bb2, u2a, z0);
                u64 pn = fma2(a1, p[r], fma2(a32, xv[r], mul2(a31, u2a)));
                z0 = fma2(a4, nv, pn);
                u64 acc = fma2(c1p, pn,
                           fma2(cw1, ns,
                            fma2(cw2, t0, mul2(c2, nv))));
                t0 = fma2(a4, t0, u2a);
                float2 ava = unpack2(acc);
                const float ye = ava.x + ava.y;

                // ---- logical column jl+1 (u_prev = u0) ----
                const float usb = u1[r];
                const u64 u2b = pack2(usb, usb);
                u64 ns2 = fma2(a1, ns, u2a);
                u64 nv2 = fma2(bb2, u2b, z1);
                u64 pn2 = fma2(a1, pn, fma2(a32, nv, mul2(a31, u2b)));
                z1 = fma2(a4, nv2, pn2);
                u64 acc2 = fma2(c1p, pn2,
                            fma2(cw1, ns2,
                             fma2(cw2, t1, mul2(c2, nv2))));
                t1 = fma2(a4, t1, u2b);
                float2 avb = unpack2(acc2);
                const float yo = avb.x + avb.y;

                // roll states past the pair
                p[r]  = pn2;
                xv[r] = nv2;
                ss[r] = ns2;
                upf[r] = usb;

                // one coalesced half2 store per row per pair
                __half2 hv = fj ? __floats2half2_rn(yo, ye)
                                : __floats2half2_rn(ye, yo);
                st_h2_cs(op + rowoff[r] + sOff, hv);
            }
            sh_z[jl][tid] = z0;
            sh_z[jl + 1][tid] = z1;
            {
                float2 g0 = unpack2(t0);
                float2 g1 = unpack2(t1);
                sh_t[jl][tid]     = __floats2half2_rn(g0.x, g0.y);
                sh_t[jl + 1][tid] = __floats2half2_rn(g1.x, g1.y);
            }

#pragma unroll
            for (int r = 0; r < 4; r++) { u0[r] = n0[r]; u1[r] = n1[r]; }
        }
    }
}

// ---------------------------------------------------------------------------
// Epilogue: out = silu( y0+y1+y2+y3 + x*omega ). Each thread: 4 e's x 2
// physical columns (one scratch pair). Scratch reads streaming uint4.
// ---------------------------------------------------------------------------
__global__ void __launch_bounds__(256) ssm_epilogue(
    const float* __restrict__ x,
    const float* __restrict__ omega,
    float* __restrict__ out)
{
    const int t  = blockIdx.x * 256 + threadIdx.x;   // 0 .. S_TOT/8
    const int e0 = (t & 255) * 4;                    // 4-aligned e
    const int bi = (t >> 8) & 15;
    const int sp = t >> 12;                          // i*16 + jpair, [0,512)

    const unsigned hb = (unsigned)sp * (BE * 2) + (unsigned)(bi * NE + e0) * 2;

    float accE[4] = {0.f, 0.f, 0.f, 0.f};
    float accO[4] = {0.f, 0.f, 0.f, 0.f};
#pragma unroll
    for (int d = 0; d < 4; d++) {
        uint4 raw = __ldcs(reinterpret_cast<const uint4*>(
            g_scrh + (size_t)d * S_TOT + hb));
        const unsigned* rw = reinterpret_cast<const unsigned*>(&raw);
#pragma unroll
        for (int k = 0; k < 4; k++) {
            __half2 hv = *reinterpret_cast<const __half2*>(&rw[k]);
            float2 fv = __half22float2(hv);
            accE[k] += fv.x;   // physical col 2*jpair
            accO[k] += fv.y;   // physical col 2*jpair+1
        }
    }

    const int s0 = sp * 2 * BE + bi * NE + e0;   // (i*32 + 2*jpair)*BE + ...
    const int s1 = s0 + BE;

    float4 x0 = *reinterpret_cast<const float4*>(x + s0);
    float4 x1 = *reinterpret_cast<const float4*>(x + s1);
    float4 om = *reinterpret_cast<const float4*>(omega + e0);

    float zE[4], zO[4];
    zE[0] = accE[0] + x0.x * om.x;  zO[0] = accO[0] + x1.x * om.x;
    zE[1] = accE[1] + x0.y * om.y;  zO[1] = accO[1] + x1.y * om.y;
    zE[2] = accE[2] + x0.z * om.z;  zO[2] = accO[2] + x1.z * om.z;
    zE[3] = accE[3] + x0.w * om.w;  zO[3] = accO[3] + x1.w * om.w;

    float4 r0, r1;
    r0.x = zE[0] / (1.0f + expf(-zE[0]));
    r0.y = zE[1] / (1.0f + expf(-zE[1]));
    r0.z = zE[2] / (1.0f + expf(-zE[2]));
    r0.w = zE[3] / (1.0f + expf(-zE[3]));
    r1.x = zO[0] / (1.0f + expf(-zO[0]));
    r1.y = zO[1] / (1.0f + expf(-zO[1]));
    r1.z = zO[2] / (1.0f + expf(-zO[2]));
    r1.w = zO[3] / (1.0f + expf(-zO[3]));
    *reinterpret_cast<float4*>(out + s0) = r0;
    *reinterpret_cast<float4*>(out + s1) = r1;
}

extern "C" void kernel_launch(void* const* d_in, const int* in_sizes, int n_in,
                              void* d_out, int out_size)
{
    const float* x   = (const float*)d_in[0];
    const float* A1v = (const float*)d_in[1];
    const float* A2v = (const float*)d_in[2];
    const float* A3v = (const float*)d_in[3];
    const float* A4v = (const float*)d_in[4];
    const float* B1v = (const float*)d_in[5];
    const float* B2v = (const float*)d_in[6];
    const float* C1v = (const float*)d_in[7];
    const float* C2v = (const float*)d_in[8];
    const float* om  = (const float*)d_in[9];
    float* out = (float*)d_out;

    // 4 dirs * 16 b * 1024 e = 65536 threads; 512 CTAs of 128 -> 1 wave,
    // 4 warps/CTA covering all 4 SMSPs.
    ssm_scan<<<512, 128>>>(x, A1v, A2v, A3v, A4v, B1v, B2v, C1v, C2v);
    ssm_epilogue<<<S_TOT / 8 / 256, 256>>>(x, om, out);
}